// round 15
// baseline (speedup 1.0000x reference)
#include <cuda_runtime.h>
#include <cstdint>

#define Bq 4
#define T 128
#define D 300
#define D4 75            // D / 4 (float4 count per row)

// Scratch for projected q (rows 0..511), k (512..1023), v (1024..1535)
__device__ __align__(16) float g_qkv[3 * Bq * T * D];

#define SSTRIDE 36                        // smem row stride (floats), 16B-aligned
#define PROJ_SMEM (2 * 300 * SSTRIDE * 4) // As + Ws bytes = 86400

// ---------------------------------------------------------------------------
// Kernel 1: BARRIER-FREE projection GEMM.
// 32x32 tile, 64 threads, 4x4 microtile. Whole k-depth (300) staged in SMEM
// once (single __syncthreads); the 300-k inner loop then free-runs with no
// barriers — 16 independent FMA chains per thread keep the FMA pipe at rt=2
// even at 1 warp/SMSP. Grid (10, 48) = 480 CTAs, 2 CTAs/SM (86.4KB smem).
// out[r,c] = A[r,:] . W[c,:] + bias[c]
// rows 0..511 -> query/WQ/bQ, 512..1023 -> key/WK/bK, 1024..1535 -> value/WK/bK
// ---------------------------------------------------------------------------
__global__ __launch_bounds__(64) void proj_kernel(
    const float* __restrict__ query, const float* __restrict__ key,
    const float* __restrict__ value,
    const float* __restrict__ WQ, const float* __restrict__ bQ,
    const float* __restrict__ WK, const float* __restrict__ bK)
{
    extern __shared__ float smem[];
    float* As = smem;                  // [300][SSTRIDE]: As[k][row]
    float* Ws = smem + 300 * SSTRIDE;  // [300][SSTRIDE]: Ws[k][col]

    const int row0 = blockIdx.y * 32;
    const int col0 = blockIdx.x * 32;
    const int tid  = threadIdx.x;      // 64 threads
    const int tx   = tid & 7;          // 8 col groups x 4 cols
    const int ty   = tid >> 3;         // 8 row groups x 4 rows

    const int sel = row0 >> 9;         // 0: query, 1: key, 2: value
    const float* Ap = (sel == 0) ? query : (sel == 1 ? key : value);
    const float* Wp = (sel == 0) ? WQ : WK;
    const float* bp = (sel == 0) ? bQ : bK;
    const int arow0 = row0 & 511;

    // ---- one-shot stage: lane = row/col (conflict-free STS), half = c parity
    const int lane = tid & 31;
    const int half = tid >> 5;         // 0 or 1
    const int gc_l = col0 + lane;
    const bool wv_ok = gc_l < D;

#pragma unroll 4
    for (int p = 0; p < 38; p++) {
        int c = p * 2 + half;          // float4 index along k
        if (c < D4) {
            float4 a = *(const float4*)&Ap[(arow0 + lane) * D + c * 4];
            As[(4 * c + 0) * SSTRIDE + lane] = a.x;
            As[(4 * c + 1) * SSTRIDE + lane] = a.y;
            As[(4 * c + 2) * SSTRIDE + lane] = a.z;
            As[(4 * c + 3) * SSTRIDE + lane] = a.w;
            float4 wv = wv_ok ? *(const float4*)&Wp[gc_l * D + c * 4]
                              : make_float4(0.f, 0.f, 0.f, 0.f);
            Ws[(4 * c + 0) * SSTRIDE + lane] = wv.x;
            Ws[(4 * c + 1) * SSTRIDE + lane] = wv.y;
            Ws[(4 * c + 2) * SSTRIDE + lane] = wv.z;
            Ws[(4 * c + 3) * SSTRIDE + lane] = wv.w;
        }
    }
    __syncthreads();                   // the ONLY barrier

    float acc[4][4];
#pragma unroll
    for (int r = 0; r < 4; r++)
#pragma unroll
        for (int c = 0; c < 4; c++) acc[r][c] = 0.f;

    const float* Ar = As + ty * 4;
    const float* Wr = Ws + tx * 4;

#pragma unroll 4
    for (int k = 0; k < 300; k++) {
        float4 av = *(const float4*)&Ar[k * SSTRIDE];
        float4 wv = *(const float4*)&Wr[k * SSTRIDE];
        float a4[4] = {av.x, av.y, av.z, av.w};
        float w4[4] = {wv.x, wv.y, wv.z, wv.w};
#pragma unroll
        for (int r = 0; r < 4; r++)
#pragma unroll
            for (int c = 0; c < 4; c++) acc[r][c] += a4[r] * w4[c];
    }

#pragma unroll
    for (int r = 0; r < 4; r++) {
        int gr = row0 + ty * 4 + r;
#pragma unroll
        for (int c = 0; c < 4; c++) {
            int gcol = col0 + tx * 4 + c;
            if (gcol < D) g_qkv[gr * D + gcol] = acc[r][c] + bp[gcol];
        }
    }
}

// ---------------------------------------------------------------------------
// Kernel 2: fused attention — round-10 winner, UNCHANGED (30.9us, DRAM 67%).
// ---------------------------------------------------------------------------
__global__ __launch_bounds__(256, 4) void attn_kernel(
    const float* __restrict__ hL, const float* __restrict__ hR,
    float* __restrict__ out)
{
    __shared__ float q_s[304];
    __shared__ float scores_s[128];
    __shared__ float listw_s[128];
    __shared__ int   listj_s[128];
    __shared__ int   cnt_s;

    const int tid  = threadIdx.x;
    const int lane = tid & 31;
    const int w    = tid >> 5;           // 8 warps
    const int b    = blockIdx.x >> 7;
    const int i    = blockIdx.x & 127;

    const float4* qkv4 = (const float4*)g_qkv;

    // ---- load q_i (L2-hot, tiny) ----
    if (tid < D4) ((float4*)q_s)[tid] = qkv4[(b * T + i) * D4 + tid];
    __syncthreads();

    const float4* q4 = (const float4*)q_s;
    const bool has_c = (lane < D4 - 64);           // lane < 11

    // ---- scoring: scores_j = sum_d (q[d]+hL[b,i,j,d]) * (k[b,j,d]+hR[b,j,i,d])
    const float4* hL4 = (const float4*)hL + (size_t)(b * T + i) * T * D4;
    const float4* hRb = (const float4*)hR + ((size_t)b * T * T + i) * D4;
    const float4* k4b = qkv4 + (Bq * T + b * T) * D4;

#pragma unroll 2
    for (int jj = 0; jj < 16; jj++) {
        const int j = w * 16 + jj;
        const float4* hl = hL4 + j * D4;
        const float4* hr = hRb + (size_t)j * T * D4;
        const float4* kp = k4b + j * D4;

        float4 l0 = hl[lane],      r0 = hr[lane],      k0 = kp[lane];
        float4 l1 = hl[lane + 32], r1 = hr[lane + 32], k1 = kp[lane + 32];
        float4 l2, r2, k2;
        if (has_c) { l2 = hl[lane + 64]; r2 = hr[lane + 64]; k2 = kp[lane + 64]; }

        float4 qa = q4[lane];
        float acc = (qa.x + l0.x) * (k0.x + r0.x) + (qa.y + l0.y) * (k0.y + r0.y)
                  + (qa.z + l0.z) * (k0.z + r0.z) + (qa.w + l0.w) * (k0.w + r0.w);
        float4 qb = q4[lane + 32];
        acc += (qb.x + l1.x) * (k1.x + r1.x) + (qb.y + l1.y) * (k1.y + r1.y)
             + (qb.z + l1.z) * (k1.z + r1.z) + (qb.w + l1.w) * (k1.w + r1.w);
        if (has_c) {
            float4 qc = q4[lane + 64];
            acc += (qc.x + l2.x) * (k2.x + r2.x) + (qc.y + l2.y) * (k2.y + r2.y)
                 + (qc.z + l2.z) * (k2.z + r2.z) + (qc.w + l2.w) * (k2.w + r2.w);
        }
#pragma unroll
        for (int o = 16; o > 0; o >>= 1)
            acc += __shfl_xor_sync(0xffffffffu, acc, o);
        if (lane == 0) scores_s[j] = acc;
    }
    __syncthreads();

    // ---- p = softmax(scores); attn = softmax(1000*p); clip is a no-op.
    // p_max = 1/sum exactly (max exp term is 1): 1000*(p-p_max) = 1000*inv*(e-1)
    // Build an ORDERED compact list of significant j (deterministic).
    if (w == 0) {
        float s0 = scores_s[lane],      s1 = scores_s[lane + 32];
        float s2 = scores_s[lane + 64], s3 = scores_s[lane + 96];
        float m = fmaxf(fmaxf(s0, s1), fmaxf(s2, s3));
#pragma unroll
        for (int o = 16; o > 0; o >>= 1)
            m = fmaxf(m, __shfl_xor_sync(0xffffffffu, m, o));
        float e0 = expf(s0 - m), e1 = expf(s1 - m);
        float e2 = expf(s2 - m), e3 = expf(s3 - m);
        float sum = e0 + e1 + e2 + e3;
#pragma unroll
        for (int o = 16; o > 0; o >>= 1)
            sum += __shfl_xor_sync(0xffffffffu, sum, o);
        float inv = 1.f / sum;
        float a0 = expf(1000.f * inv * (e0 - 1.f));
        float a1 = expf(1000.f * inv * (e1 - 1.f));
        float a2 = expf(1000.f * inv * (e2 - 1.f));
        float a3 = expf(1000.f * inv * (e3 - 1.f));
        float sum2 = a0 + a1 + a2 + a3;
#pragma unroll
        for (int o = 16; o > 0; o >>= 1)
            sum2 += __shfl_xor_sync(0xffffffffu, sum2, o);
        float inv2 = 1.f / sum2;

        float av[4] = {a0 * inv2, a1 * inv2, a2 * inv2, a3 * inv2};
        int base = 0;
#pragma unroll
        for (int qd = 0; qd < 4; qd++) {
            bool f = av[qd] > 1e-12f;
            unsigned mask = __ballot_sync(0xffffffffu, f);
            int pos = base + __popc(mask & ((1u << lane) - 1u));
            if (f) { listj_s[pos] = qd * 32 + lane; listw_s[pos] = av[qd]; }
            base += __popc(mask);
        }
        if (lane == 0) cnt_s = base;
    }
    __syncthreads();

    // ---- output: out[b,i,d] = sum over significant j of a_j*(v[j,d]+hR[j,i,d])
    const float* vg  = g_qkv + (size_t)(2 * Bq * T + b * T) * D;
    const float* hRs = hR + ((size_t)b * T * T + i) * D;
    const int cnt = cnt_s;
#pragma unroll
    for (int rep = 0; rep < 2; rep++) {
        int d = tid + rep * 256;
        if (d < D) {
            float acc = 0.f;
            for (int t = 0; t < cnt; t++) {
                int   j = listj_s[t];
                float a = listw_s[t];
                acc += a * (vg[j * D + d] + hRs[(size_t)j * T * D + d]);
            }
            out[(b * T + i) * D + d] = acc;
        }
    }
}

// ---------------------------------------------------------------------------
extern "C" void kernel_launch(void* const* d_in, const int* in_sizes, int n_in,
                              void* d_out, int out_size)
{
    const float* query = (const float*)d_in[0];
    const float* key   = (const float*)d_in[1];
    const float* value = (const float*)d_in[2];
    const float* hL    = (const float*)d_in[3];
    const float* hR    = (const float*)d_in[4];
    const float* WQ    = (const float*)d_in[5];
    const float* bQ    = (const float*)d_in[6];
    const float* WK    = (const float*)d_in[7];
    const float* bK    = (const float*)d_in[8];
    float* out = (float*)d_out;

    cudaFuncSetAttribute(proj_kernel,
                         cudaFuncAttributeMaxDynamicSharedMemorySize,
                         PROJ_SMEM);

    // 1536 rows x 300 cols: 48 row tiles x 10 col tiles of 32 = 480 CTAs
    proj_kernel<<<dim3(10, 48), 64, PROJ_SMEM>>>(query, key, value,
                                                 WQ, bQ, WK, bK);
    attn_kernel<<<Bq * T, 256>>>(hL, hR, out);
}

// round 16
// speedup vs baseline: 1.8043x; 1.8043x over previous
#include <cuda_runtime.h>
#include <cstdint>

#define Bq 4
#define T 128
#define D 300
#define D4 75            // D / 4 (float4 count per row)

// Scratch for projected q (rows 0..511), k (512..1023), v (1024..1535)
__device__ __align__(16) float g_qkv[3 * Bq * T * D];

// ---------------------------------------------------------------------------
// Kernel 1: batched projection GEMM — round-10 version, FROZEN (best: 18.3us,
// ~1.3x its LDS-bandwidth floor; 6 alternative shapes all measured worse).
// 32x32 tiles, 128 threads, 4x2 microtile, k-chunk 32, double-buffered,
// swizzled smem. Grid (10, 48) = 480 CTAs.
// ---------------------------------------------------------------------------
__global__ __launch_bounds__(128) void proj_kernel(
    const float* __restrict__ query, const float* __restrict__ key,
    const float* __restrict__ value,
    const float* __restrict__ WQ, const float* __restrict__ bQ,
    const float* __restrict__ WK, const float* __restrict__ bK)
{
    __shared__ float A_s[2][32][36];
    __shared__ float W_s[2][32][36];

    const int row0 = blockIdx.y * 32;
    const int col0 = blockIdx.x * 32;
    const int tid  = threadIdx.x;
    const int tx   = tid & 15;
    const int ty   = tid >> 4;

    const int sel = row0 >> 9;    // 0: query, 1: key, 2: value
    const float* Ap = (sel == 0) ? query : (sel == 1 ? key : value);
    const float* Wp = (sel == 0) ? WQ : WK;
    const float* bp = (sel == 0) ? bQ : bK;
    const int arow0 = row0 & 511;

    const int lm = tid >> 3;          // 0..15
    const int lk = (tid & 7) * 4;     // 0,4,..,28

    const int NC = (D + 31) / 32;
    float4 a_r[2], w_r[2];

    auto fetch = [&](int k0) {
        bool kv = (k0 + lk) < D;
#pragma unroll
        for (int p = 0; p < 2; p++) {
            int r = lm + p * 16;
            a_r[p] = kv ? *(const float4*)&Ap[(arow0 + r) * D + k0 + lk]
                        : make_float4(0.f, 0.f, 0.f, 0.f);
            int gc = col0 + r;
            w_r[p] = (kv && gc < D) ? *(const float4*)&Wp[gc * D + k0 + lk]
                                    : make_float4(0.f, 0.f, 0.f, 0.f);
        }
    };
    auto store = [&](int buf) {
#pragma unroll
        for (int p = 0; p < 2; p++) {
            int r   = lm + p * 16;
            int col = (r + lk) & 31;          // swizzle
            A_s[buf][lk + 0][col] = a_r[p].x; A_s[buf][lk + 1][col] = a_r[p].y;
            A_s[buf][lk + 2][col] = a_r[p].z; A_s[buf][lk + 3][col] = a_r[p].w;
            W_s[buf][lk + 0][col] = w_r[p].x; W_s[buf][lk + 1][col] = w_r[p].y;
            W_s[buf][lk + 2][col] = w_r[p].z; W_s[buf][lk + 3][col] = w_r[p].w;
        }
    };

    float acc[4][2];
#pragma unroll
    for (int r = 0; r < 4; r++) { acc[r][0] = 0.f; acc[r][1] = 0.f; }

    fetch(0);
    store(0);
    __syncthreads();

    for (int ch = 0; ch < NC; ch++) {
        const int buf = ch & 1;
        if (ch + 1 < NC) fetch((ch + 1) * 32);
#pragma unroll
        for (int e = 0; e < 32; e++) {
            const int off = e & ~3;
            float4 av = *(const float4*)&A_s[buf][e][(ty * 4 + off) & 31];
            float2 wv = *(const float2*)&W_s[buf][e][(tx * 2 + off) & 31];
            acc[0][0] += av.x * wv.x; acc[0][1] += av.x * wv.y;
            acc[1][0] += av.y * wv.x; acc[1][1] += av.y * wv.y;
            acc[2][0] += av.z * wv.x; acc[2][1] += av.z * wv.y;
            acc[3][0] += av.w * wv.x; acc[3][1] += av.w * wv.y;
        }
        if (ch + 1 < NC) store(1 - buf);
        __syncthreads();
    }

#pragma unroll
    for (int r = 0; r < 4; r++) {
        int gr = row0 + ty * 4 + r;
#pragma unroll
        for (int c = 0; c < 2; c++) {
            int gcol = col0 + tx * 2 + c;
            if (gcol < D) g_qkv[gr * D + gcol] = acc[r][c] + bp[gcol];
        }
    }
}

// ---------------------------------------------------------------------------
// Kernel 2: fused attention — round-10 winner with ONE change: single-use
// hL/hR stream loads use __ldcs (evict-first) so L1 is preserved for the
// heavily re-read k rows and q, shortening each j-iteration's L2 trips.
// ---------------------------------------------------------------------------
__global__ __launch_bounds__(256, 4) void attn_kernel(
    const float* __restrict__ hL, const float* __restrict__ hR,
    float* __restrict__ out)
{
    __shared__ float q_s[304];
    __shared__ float scores_s[128];
    __shared__ float listw_s[128];
    __shared__ int   listj_s[128];
    __shared__ int   cnt_s;

    const int tid  = threadIdx.x;
    const int lane = tid & 31;
    const int w    = tid >> 5;           // 8 warps
    const int b    = blockIdx.x >> 7;
    const int i    = blockIdx.x & 127;

    const float4* qkv4 = (const float4*)g_qkv;

    // ---- load q_i (L2-hot, tiny) ----
    if (tid < D4) ((float4*)q_s)[tid] = qkv4[(b * T + i) * D4 + tid];
    __syncthreads();

    const float4* q4 = (const float4*)q_s;
    const bool has_c = (lane < D4 - 64);           // lane < 11

    // ---- scoring: scores_j = sum_d (q[d]+hL[b,i,j,d]) * (k[b,j,d]+hR[b,j,i,d])
    const float4* hL4 = (const float4*)hL + (size_t)(b * T + i) * T * D4;
    const float4* hRb = (const float4*)hR + ((size_t)b * T * T + i) * D4;
    const float4* k4b = qkv4 + (Bq * T + b * T) * D4;

#pragma unroll 2
    for (int jj = 0; jj < 16; jj++) {
        const int j = w * 16 + jj;
        const float4* hl = hL4 + j * D4;
        const float4* hr = hRb + (size_t)j * T * D4;
        const float4* kp = k4b + j * D4;

        float4 l0 = __ldcs(hl + lane);
        float4 r0 = __ldcs(hr + lane);
        float4 k0 = kp[lane];
        float4 l1 = __ldcs(hl + lane + 32);
        float4 r1 = __ldcs(hr + lane + 32);
        float4 k1 = kp[lane + 32];
        float4 l2, r2, k2;
        if (has_c) {
            l2 = __ldcs(hl + lane + 64);
            r2 = __ldcs(hr + lane + 64);
            k2 = kp[lane + 64];
        }

        float4 qa = q4[lane];
        float acc = (qa.x + l0.x) * (k0.x + r0.x) + (qa.y + l0.y) * (k0.y + r0.y)
                  + (qa.z + l0.z) * (k0.z + r0.z) + (qa.w + l0.w) * (k0.w + r0.w);
        float4 qb = q4[lane + 32];
        acc += (qb.x + l1.x) * (k1.x + r1.x) + (qb.y + l1.y) * (k1.y + r1.y)
             + (qb.z + l1.z) * (k1.z + r1.z) + (qb.w + l1.w) * (k1.w + r1.w);
        if (has_c) {
            float4 qc = q4[lane + 64];
            acc += (qc.x + l2.x) * (k2.x + r2.x) + (qc.y + l2.y) * (k2.y + r2.y)
                 + (qc.z + l2.z) * (k2.z + r2.z) + (qc.w + l2.w) * (k2.w + r2.w);
        }
#pragma unroll
        for (int o = 16; o > 0; o >>= 1)
            acc += __shfl_xor_sync(0xffffffffu, acc, o);
        if (lane == 0) scores_s[j] = acc;
    }
    __syncthreads();

    // ---- p = softmax(scores); attn = softmax(1000*p); clip is a no-op.
    // p_max = 1/sum exactly (max exp term is 1): 1000*(p-p_max) = 1000*inv*(e-1)
    // Build an ORDERED compact list of significant j (deterministic).
    if (w == 0) {
        float s0 = scores_s[lane],      s1 = scores_s[lane + 32];
        float s2 = scores_s[lane + 64], s3 = scores_s[lane + 96];
        float m = fmaxf(fmaxf(s0, s1), fmaxf(s2, s3));
#pragma unroll
        for (int o = 16; o > 0; o >>= 1)
            m = fmaxf(m, __shfl_xor_sync(0xffffffffu, m, o));
        float e0 = expf(s0 - m), e1 = expf(s1 - m);
        float e2 = expf(s2 - m), e3 = expf(s3 - m);
        float sum = e0 + e1 + e2 + e3;
#pragma unroll
        for (int o = 16; o > 0; o >>= 1)
            sum += __shfl_xor_sync(0xffffffffu, sum, o);
        float inv = 1.f / sum;
        float a0 = expf(1000.f * inv * (e0 - 1.f));
        float a1 = expf(1000.f * inv * (e1 - 1.f));
        float a2 = expf(1000.f * inv * (e2 - 1.f));
        float a3 = expf(1000.f * inv * (e3 - 1.f));
        float sum2 = a0 + a1 + a2 + a3;
#pragma unroll
        for (int o = 16; o > 0; o >>= 1)
            sum2 += __shfl_xor_sync(0xffffffffu, sum2, o);
        float inv2 = 1.f / sum2;

        float av[4] = {a0 * inv2, a1 * inv2, a2 * inv2, a3 * inv2};
        int base = 0;
#pragma unroll
        for (int qd = 0; qd < 4; qd++) {
            bool f = av[qd] > 1e-12f;
            unsigned mask = __ballot_sync(0xffffffffu, f);
            int pos = base + __popc(mask & ((1u << lane) - 1u));
            if (f) { listj_s[pos] = qd * 32 + lane; listw_s[pos] = av[qd]; }
            base += __popc(mask);
        }
        if (lane == 0) cnt_s = base;
    }
    __syncthreads();

    // ---- output: out[b,i,d] = sum over significant j of a_j*(v[j,d]+hR[j,i,d])
    const float* vg  = g_qkv + (size_t)(2 * Bq * T + b * T) * D;
    const float* hRs = hR + ((size_t)b * T * T + i) * D;
    const int cnt = cnt_s;
#pragma unroll
    for (int rep = 0; rep < 2; rep++) {
        int d = tid + rep * 256;
        if (d < D) {
            float acc = 0.f;
            for (int t = 0; t < cnt; t++) {
                int   j = listj_s[t];
                float a = listw_s[t];
                acc += a * (vg[j * D + d] + hRs[(size_t)j * T * D + d]);
            }
            out[(b * T + i) * D + d] = acc;
        }
    }
}

// ---------------------------------------------------------------------------
extern "C" void kernel_launch(void* const* d_in, const int* in_sizes, int n_in,
                              void* d_out, int out_size)
{
    const float* query = (const float*)d_in[0];
    const float* key   = (const float*)d_in[1];
    const float* value = (const float*)d_in[2];
    const float* hL    = (const float*)d_in[3];
    const float* hR    = (const float*)d_in[4];
    const float* WQ    = (const float*)d_in[5];
    const float* bQ    = (const float*)d_in[6];
    const float* WK    = (const float*)d_in[7];
    const float* bK    = (const float*)d_in[8];
    float* out = (float*)d_out;

    // 1536 rows x 300 cols: 48 row tiles x 10 col tiles of 32 = 480 CTAs
    proj_kernel<<<dim3(10, 48), 128>>>(query, key, value, WQ, bQ, WK, bK);
    attn_kernel<<<Bq * T, 256>>>(hL, hR, out);
}

// round 17
// speedup vs baseline: 1.8674x; 1.0350x over previous
#include <cuda_runtime.h>
#include <cstdint>

#define Bq 4
#define T 128
#define D 300
#define D4 75            // D / 4 (float4 count per row)

// Scratch for projected q (rows 0..511), k (512..1023), v (1024..1535)
__device__ __align__(16) float g_qkv[3 * Bq * T * D];
__device__ float g_sink[512];     // DCE-blocker for the prefetch branch

#define PREF_CTAS 480
#define HL_FLOAT4 (Bq * T * T * D4)          // 4,915,200 float4 in hL

// ---------------------------------------------------------------------------
// Kernel 1: fused {L2-prefetch of hL} + {projection GEMM}.
//  - blocks [0, 480): stream a contiguous slice of hL through L2 (__ldcg).
//    Pure-MLP CTAs that soak the DRAM bandwidth proj leaves idle (1.7%).
//  - blocks [480, 960): round-10 proj GEMM (frozen best: 32x32 tiles, 128
//    thr, 4x2 microtile, k-chunk 32, double-buffered, swizzled smem).
// ---------------------------------------------------------------------------
__global__ __launch_bounds__(128) void proj_prefetch_kernel(
    const float* __restrict__ query, const float* __restrict__ key,
    const float* __restrict__ value, const float* __restrict__ hL,
    const float* __restrict__ WQ, const float* __restrict__ bQ,
    const float* __restrict__ WK, const float* __restrict__ bK)
{
    __shared__ float A_s[2][32][36];
    __shared__ float W_s[2][32][36];

    const int tid = threadIdx.x;

    if (blockIdx.x < PREF_CTAS) {
        // ---------------- prefetch branch: warm L2 with hL ----------------
        const float4* src = (const float4*)hL;
        const int per = (HL_FLOAT4 + PREF_CTAS - 1) / PREF_CTAS;   // 10240
        int beg = blockIdx.x * per;
        int end = beg + per; if (end > HL_FLOAT4) end = HL_FLOAT4;
        float acc = 0.f;
        for (int idx = beg + tid; idx < end; idx += 128) {
            float4 v = __ldcg(src + idx);
            acc += (v.x + v.y) + (v.z + v.w);
        }
        // never taken for finite input sums vs sentinel; keeps loads live
        if (acc == -1.234567e35f) g_sink[blockIdx.x & 511] = acc;
        return;
    }

    // ---------------- proj branch (round-10, frozen) ----------------
    const int bx   = blockIdx.x - PREF_CTAS;
    const int row0 = (bx / 10) * 32;
    const int col0 = (bx % 10) * 32;
    const int tx   = tid & 15;
    const int ty   = tid >> 4;

    const int sel = row0 >> 9;    // 0: query, 1: key, 2: value
    const float* Ap = (sel == 0) ? query : (sel == 1 ? key : value);
    const float* Wp = (sel == 0) ? WQ : WK;
    const float* bp = (sel == 0) ? bQ : bK;
    const int arow0 = row0 & 511;

    const int lm = tid >> 3;          // 0..15
    const int lk = (tid & 7) * 4;     // 0,4,..,28

    const int NC = (D + 31) / 32;
    float4 a_r[2], w_r[2];

    auto fetch = [&](int k0) {
        bool kv = (k0 + lk) < D;
#pragma unroll
        for (int p = 0; p < 2; p++) {
            int r = lm + p * 16;
            a_r[p] = kv ? *(const float4*)&Ap[(arow0 + r) * D + k0 + lk]
                        : make_float4(0.f, 0.f, 0.f, 0.f);
            int gc = col0 + r;
            w_r[p] = (kv && gc < D) ? *(const float4*)&Wp[gc * D + k0 + lk]
                                    : make_float4(0.f, 0.f, 0.f, 0.f);
        }
    };
    auto store = [&](int buf) {
#pragma unroll
        for (int p = 0; p < 2; p++) {
            int r   = lm + p * 16;
            int col = (r + lk) & 31;          // swizzle
            A_s[buf][lk + 0][col] = a_r[p].x; A_s[buf][lk + 1][col] = a_r[p].y;
            A_s[buf][lk + 2][col] = a_r[p].z; A_s[buf][lk + 3][col] = a_r[p].w;
            W_s[buf][lk + 0][col] = w_r[p].x; W_s[buf][lk + 1][col] = w_r[p].y;
            W_s[buf][lk + 2][col] = w_r[p].z; W_s[buf][lk + 3][col] = w_r[p].w;
        }
    };

    float acc[4][2];
#pragma unroll
    for (int r = 0; r < 4; r++) { acc[r][0] = 0.f; acc[r][1] = 0.f; }

    fetch(0);
    store(0);
    __syncthreads();

    for (int ch = 0; ch < NC; ch++) {
        const int buf = ch & 1;
        if (ch + 1 < NC) fetch((ch + 1) * 32);
#pragma unroll
        for (int e = 0; e < 32; e++) {
            const int off = e & ~3;
            float4 av = *(const float4*)&A_s[buf][e][(ty * 4 + off) & 31];
            float2 wv = *(const float2*)&W_s[buf][e][(tx * 2 + off) & 31];
            acc[0][0] += av.x * wv.x; acc[0][1] += av.x * wv.y;
            acc[1][0] += av.y * wv.x; acc[1][1] += av.y * wv.y;
            acc[2][0] += av.z * wv.x; acc[2][1] += av.z * wv.y;
            acc[3][0] += av.w * wv.x; acc[3][1] += av.w * wv.y;
        }
        if (ch + 1 < NC) store(1 - buf);
        __syncthreads();
    }

#pragma unroll
    for (int r = 0; r < 4; r++) {
        int gr = row0 + ty * 4 + r;
#pragma unroll
        for (int c = 0; c < 2; c++) {
            int gcol = col0 + tx * 2 + c;
            if (gcol < D) g_qkv[gr * D + gcol] = acc[r][c] + bp[gcol];
        }
    }
}

// ---------------------------------------------------------------------------
// Kernel 2: fused attention — round-10 winner, byte-identical (30.9us).
// hL now largely L2-resident thanks to the prefetch branch.
// ---------------------------------------------------------------------------
__global__ __launch_bounds__(256, 4) void attn_kernel(
    const float* __restrict__ hL, const float* __restrict__ hR,
    float* __restrict__ out)
{
    __shared__ float q_s[304];
    __shared__ float scores_s[128];
    __shared__ float listw_s[128];
    __shared__ int   listj_s[128];
    __shared__ int   cnt_s;

    const int tid  = threadIdx.x;
    const int lane = tid & 31;
    const int w    = tid >> 5;           // 8 warps
    const int b    = blockIdx.x >> 7;
    const int i    = blockIdx.x & 127;

    const float4* qkv4 = (const float4*)g_qkv;

    // ---- load q_i (L2-hot, tiny) ----
    if (tid < D4) ((float4*)q_s)[tid] = qkv4[(b * T + i) * D4 + tid];
    __syncthreads();

    const float4* q4 = (const float4*)q_s;
    const bool has_c = (lane < D4 - 64);           // lane < 11

    // ---- scoring: scores_j = sum_d (q[d]+hL[b,i,j,d]) * (k[b,j,d]+hR[b,j,i,d])
    const float4* hL4 = (const float4*)hL + (size_t)(b * T + i) * T * D4;
    const float4* hRb = (const float4*)hR + ((size_t)b * T * T + i) * D4;
    const float4* k4b = qkv4 + (Bq * T + b * T) * D4;

#pragma unroll 2
    for (int jj = 0; jj < 16; jj++) {
        const int j = w * 16 + jj;
        const float4* hl = hL4 + j * D4;
        const float4* hr = hRb + (size_t)j * T * D4;
        const float4* kp = k4b + j * D4;

        float4 l0 = hl[lane],      r0 = hr[lane],      k0 = kp[lane];
        float4 l1 = hl[lane + 32], r1 = hr[lane + 32], k1 = kp[lane + 32];
        float4 l2, r2, k2;
        if (has_c) { l2 = hl[lane + 64]; r2 = hr[lane + 64]; k2 = kp[lane + 64]; }

        float4 qa = q4[lane];
        float acc = (qa.x + l0.x) * (k0.x + r0.x) + (qa.y + l0.y) * (k0.y + r0.y)
                  + (qa.z + l0.z) * (k0.z + r0.z) + (qa.w + l0.w) * (k0.w + r0.w);
        float4 qb = q4[lane + 32];
        acc += (qb.x + l1.x) * (k1.x + r1.x) + (qb.y + l1.y) * (k1.y + r1.y)
             + (qb.z + l1.z) * (k1.z + r1.z) + (qb.w + l1.w) * (k1.w + r1.w);
        if (has_c) {
            float4 qc = q4[lane + 64];
            acc += (qc.x + l2.x) * (k2.x + r2.x) + (qc.y + l2.y) * (k2.y + r2.y)
                 + (qc.z + l2.z) * (k2.z + r2.z) + (qc.w + l2.w) * (k2.w + r2.w);
        }
#pragma unroll
        for (int o = 16; o > 0; o >>= 1)
            acc += __shfl_xor_sync(0xffffffffu, acc, o);
        if (lane == 0) scores_s[j] = acc;
    }
    __syncthreads();

    // ---- p = softmax(scores); attn = softmax(1000*p); clip is a no-op.
    // p_max = 1/sum exactly (max exp term is 1): 1000*(p-p_max) = 1000*inv*(e-1)
    // Build an ORDERED compact list of significant j (deterministic).
    if (w == 0) {
        float s0 = scores_s[lane],      s1 = scores_s[lane + 32];
        float s2 = scores_s[lane + 64], s3 = scores_s[lane + 96];
        float m = fmaxf(fmaxf(s0, s1), fmaxf(s2, s3));
#pragma unroll
        for (int o = 16; o > 0; o >>= 1)
            m = fmaxf(m, __shfl_xor_sync(0xffffffffu, m, o));
        float e0 = expf(s0 - m), e1 = expf(s1 - m);
        float e2 = expf(s2 - m), e3 = expf(s3 - m);
        float sum = e0 + e1 + e2 + e3;
#pragma unroll
        for (int o = 16; o > 0; o >>= 1)
            sum += __shfl_xor_sync(0xffffffffu, sum, o);
        float inv = 1.f / sum;
        float a0 = expf(1000.f * inv * (e0 - 1.f));
        float a1 = expf(1000.f * inv * (e1 - 1.f));
        float a2 = expf(1000.f * inv * (e2 - 1.f));
        float a3 = expf(1000.f * inv * (e3 - 1.f));
        float sum2 = a0 + a1 + a2 + a3;
#pragma unroll
        for (int o = 16; o > 0; o >>= 1)
            sum2 += __shfl_xor_sync(0xffffffffu, sum2, o);
        float inv2 = 1.f / sum2;

        float av[4] = {a0 * inv2, a1 * inv2, a2 * inv2, a3 * inv2};
        int base = 0;
#pragma unroll
        for (int qd = 0; qd < 4; qd++) {
            bool f = av[qd] > 1e-12f;
            unsigned mask = __ballot_sync(0xffffffffu, f);
            int pos = base + __popc(mask & ((1u << lane) - 1u));
            if (f) { listj_s[pos] = qd * 32 + lane; listw_s[pos] = av[qd]; }
            base += __popc(mask);
        }
        if (lane == 0) cnt_s = base;
    }
    __syncthreads();

    // ---- output: out[b,i,d] = sum over significant j of a_j*(v[j,d]+hR[j,i,d])
    const float* vg  = g_qkv + (size_t)(2 * Bq * T + b * T) * D;
    const float* hRs = hR + ((size_t)b * T * T + i) * D;
    const int cnt = cnt_s;
#pragma unroll
    for (int rep = 0; rep < 2; rep++) {
        int d = tid + rep * 256;
        if (d < D) {
            float acc = 0.f;
            for (int t = 0; t < cnt; t++) {
                int   j = listj_s[t];
                float a = listw_s[t];
                acc += a * (vg[j * D + d] + hRs[(size_t)j * T * D + d]);
            }
            out[(b * T + i) * D + d] = acc;
        }
    }
}

// ---------------------------------------------------------------------------
extern "C" void kernel_launch(void* const* d_in, const int* in_sizes, int n_in,
                              void* d_out, int out_size)
{
    const float* query = (const float*)d_in[0];
    const float* key   = (const float*)d_in[1];
    const float* value = (const float*)d_in[2];
    const float* hL    = (const float*)d_in[3];
    const float* hR    = (const float*)d_in[4];
    const float* WQ    = (const float*)d_in[5];
    const float* bQ    = (const float*)d_in[6];
    const float* WK    = (const float*)d_in[7];
    const float* bK    = (const float*)d_in[8];
    float* out = (float*)d_out;

    // 480 hL-prefetch CTAs + 480 proj CTAs in one grid
    proj_prefetch_kernel<<<2 * PREF_CTAS, 128>>>(query, key, value, hL,
                                                 WQ, bQ, WK, bK);
    attn_kernel<<<Bq * T, 256>>>(hL, hR, out);
}